// round 5
// baseline (speedup 1.0000x reference)
#include <cuda_runtime.h>

#define U_N 200000
#define M_N 100000
#define E_N 2000000
#define HD 64
#define CN 7
#define NTOT (U_N + M_N)

// ---------------- device scratch (static; zero-initialized at module load) ----------------
// d_deg and d_lb_flag are re-zeroed at the END of every kernel_launch (tail
// blocks of k_classify), so every graph replay starts from a clean state.
__device__ int d_deg[NTOT];
__device__ int d_off_u[U_N + 1];
__device__ int d_off_m[M_N + 1];
__device__ int d_cur_u[U_N];
__device__ int d_cur_m[M_N];
__device__ int d_nbr_u[E_N];
__device__ int d_nbr_m[E_N];
__device__ volatile int d_lb_flag[512];
__device__ int d_lb_agg[512];
__device__ int d_lb_inc[512];
// activation buffers: [N][128] floats, row = [agg(64) | xd(64)]
__device__ float4 d_act_u1[(size_t)U_N * 32];
__device__ float4 d_act_m1[(size_t)M_N * 32];
__device__ float4 d_act_u2[(size_t)U_N * 32];
__device__ float4 d_act_m2[(size_t)M_N * 32];
// final layer-2 outputs: [N][64]
__device__ float4 d_u2o[(size_t)U_N * 16];
__device__ float4 d_m2o[(size_t)M_N * 16];

// ---------------- helpers ----------------
__device__ __forceinline__ int ldidx(const void* p, int i, int f64) {
    return f64 ? (int)((const long long*)p)[i] : ((const int*)p)[i];
}
__device__ __forceinline__ int detect64(const int* uw) { return uw[3] == 0; }

__device__ __forceinline__ unsigned long long pack2(float x, float y) {
    unsigned long long r;
    asm("mov.b64 %0, {%1, %2};" : "=l"(r) : "f"(x), "f"(y));
    return r;
}
__device__ __forceinline__ float2 unpack2(unsigned long long v) {
    float2 r;
    asm("mov.b64 {%0, %1}, %2;" : "=f"(r.x), "=f"(r.y) : "l"(v));
    return r;
}
__device__ __forceinline__ void ffma2(unsigned long long& acc, unsigned long long a,
                                      unsigned long long w) {
    asm("fma.rn.f32x2 %0, %1, %2, %0;" : "+l"(acc) : "l"(a), "l"(w));
}

// ---------------- launch 0: user gather + movie projection + degree count ----------------
__global__ __launch_bounds__(256) void k_prep(
    const int* uw, const void* unid, const void* mnid,
    const float* ue, const float* mx, const float* W, const float* bb,
    const float* memb, const void* es, const void* ed,
    int U, int M, int F, int E, int GG, int GM, int GC) {
    __shared__ float2 sW[32 * 32];
    int f64 = detect64(uw);
    if ((int)blockIdx.x < GG) {
        // x_user -> xd slot of act_u1
        int j = blockIdx.x * 256 + threadIdx.x;
        if (j < U * 16) {
            int node = j >> 4, q = j & 15;
            int uid = ldidx(unid, node, f64);
            d_act_u1[(size_t)node * 32 + 16 + q] =
                reinterpret_cast<const float4*>(ue)[(size_t)uid * 16 + q];
        }
    } else if ((int)blockIdx.x < GG + GM) {
        // x_movie = movie_x @ w_movie + b + movie_emb[id] -> xd slot of act_m1
        for (int idx = threadIdx.x; idx < F * 32; idx += 256) {
            int f = idx >> 5, t = idx & 31;
            sW[idx] = make_float2(W[f * HD + t], W[f * HD + t + 32]);
        }
        __syncthreads();
        int lane = threadIdx.x & 31, warp = threadIdx.x >> 5;
        int mb = blockIdx.x - GG;
        float* actm = reinterpret_cast<float*>(d_act_m1);
        for (int m = mb * 8 + warp; m < M; m += GM * 8) {
            float mxv = (lane < F) ? mx[(size_t)m * F + lane] : 0.f;
            int mid = ldidx(mnid, m, f64);
            float acc0 = bb[lane] + memb[(size_t)mid * HD + lane];
            float acc1 = bb[lane + 32] + memb[(size_t)mid * HD + lane + 32];
            for (int f = 0; f < F; f++) {
                float v = __shfl_sync(0xffffffffu, mxv, f);
                float2 wv = sW[f * 32 + lane];
                acc0 += v * wv.x;
                acc1 += v * wv.y;
            }
            actm[(size_t)m * 128 + 64 + lane] = acc0;
            actm[(size_t)m * 128 + 96 + lane] = acc1;
        }
    } else {
        int cb = blockIdx.x - (GG + GM);
        for (int e = cb * 256 + threadIdx.x; e < E; e += GC * 256) {
            atomicAdd(&d_deg[ldidx(es, e, f64)], 1);
            atomicAdd(&d_deg[U + ldidx(ed, e, f64)], 1);
        }
    }
}

// ---------------- launch 1: decoupled-lookback scan over combined deg ----------------
__global__ __launch_bounds__(1024) void k_scan_lb(int U, int M, int E) {
    __shared__ int sh[1024];
    __shared__ int sRun;
    int n = U + M;
    int tid = threadIdx.x, bid = blockIdx.x;
    int base = bid * 4096 + tid * 4;
    int4 v = make_int4(0, 0, 0, 0);
    if (base + 3 < n)
        v = *reinterpret_cast<const int4*>(d_deg + base);
    else {
        if (base < n) v.x = d_deg[base];
        if (base + 1 < n) v.y = d_deg[base + 1];
        if (base + 2 < n) v.z = d_deg[base + 2];
    }
    int loc = v.x + v.y + v.z + v.w;
    sh[tid] = loc;
    __syncthreads();
    for (int o = 1; o < 1024; o <<= 1) {
        int a = (tid >= o) ? sh[tid - o] : 0;
        __syncthreads();
        sh[tid] += a;
        __syncthreads();
    }
    int incl = sh[tid];
    int bsum = sh[1023];
    if (tid == 0) {
        int run = 0;
        if (bid == 0) {
            d_lb_inc[0] = bsum;
            __threadfence();
            d_lb_flag[0] = 2;
        } else {
            d_lb_agg[bid] = bsum;
            __threadfence();
            d_lb_flag[bid] = 1;
            int p = bid - 1;
            while (true) {
                int f;
                while ((f = d_lb_flag[p]) == 0) {}
                __threadfence();
                if (f == 2) { run += d_lb_inc[p]; break; }
                run += d_lb_agg[p];
                p--;
            }
            d_lb_inc[bid] = run + bsum;
            __threadfence();
            d_lb_flag[bid] = 2;
        }
        sRun = run;
    }
    __syncthreads();
    int e = sRun + incl - loc;
    int vv[4] = {v.x, v.y, v.z, v.w};
#pragma unroll
    for (int w = 0; w < 4; w++) {
        int gi = base + w;
        if (gi < n) {
            if (gi < U) { d_off_u[gi] = e; d_cur_u[gi] = e; }
            else { d_off_m[gi - U] = e - E; d_cur_m[gi - U] = e - E; }
        }
        e += vv[w];
    }
    if (bid == 0 && tid == 0) { d_off_u[U] = E; d_off_m[M] = E; }
}

// ---------------- launch 2: fill adjacency ----------------
__global__ void k_fill(const int* uw, const void* es, const void* ed, int n) {
    int f64 = detect64(uw);
    for (int e = blockIdx.x * blockDim.x + threadIdx.x; e < n;
         e += gridDim.x * blockDim.x) {
        int s = ldidx(es, e, f64);
        int d = ldidx(ed, e, f64);
        d_nbr_u[atomicAdd(&d_cur_u[s], 1)] = d;
        d_nbr_m[atomicAdd(&d_cur_m[d], 1)] = s;
    }
}

// ---------------- combined gather: both directions in one launch ----------------
// Half-warp scheme: lanes 0-15 read neighbor A's full 64-float row (float4 each),
// lanes 16-31 neighbor B; cross-half shfl_xor(16) reduce; lanes 0-15 store.
__global__ __launch_bounds__(256) void k_gather2(
    const float4* __restrict__ srcU, float* __restrict__ dstU,
    const int* __restrict__ offU, const int* __restrict__ nbrU, int nU,
    const float4* __restrict__ srcM, float* __restrict__ dstM,
    const int* __restrict__ offM, const int* __restrict__ nbrM, int nM) {
    int lane = threadIdx.x & 31, warp = threadIdx.x >> 5;
    int half = lane >> 4, l16 = lane & 15;
    int ntot = nU + nM;
    for (int ii = blockIdx.x * 8 + warp; ii < ntot; ii += gridDim.x * 8) {
        const float4* src;
        float* dst;
        const int* off;
        const int* nbr;
        int i;
        if (ii < nU) { src = srcU; dst = dstU; off = offU; nbr = nbrU; i = ii; }
        else { src = srcM; dst = dstM; off = offM; nbr = nbrM; i = ii - nU; }
        int s0 = off[i], s1 = off[i + 1];
        float4 acc = make_float4(0.f, 0.f, 0.f, 0.f);
        for (int j = s0; j < s1; j += 32) {
            int myn = (j + lane < s1) ? nbr[j + lane] : 0;
            int cnt = min(32, s1 - j);
            int jj = 0;
            for (; jj + 8 <= cnt; jj += 8) {
                int n0 = __shfl_sync(0xffffffffu, myn, jj + half);
                int n1 = __shfl_sync(0xffffffffu, myn, jj + 2 + half);
                int n2 = __shfl_sync(0xffffffffu, myn, jj + 4 + half);
                int n3 = __shfl_sync(0xffffffffu, myn, jj + 6 + half);
                float4 v0 = src[(size_t)n0 * 32 + l16];
                float4 v1 = src[(size_t)n1 * 32 + l16];
                float4 v2 = src[(size_t)n2 * 32 + l16];
                float4 v3 = src[(size_t)n3 * 32 + l16];
                acc.x += (v0.x + v1.x) + (v2.x + v3.x);
                acc.y += (v0.y + v1.y) + (v2.y + v3.y);
                acc.z += (v0.z + v1.z) + (v2.z + v3.z);
                acc.w += (v0.w + v1.w) + (v2.w + v3.w);
            }
            for (; jj + 2 <= cnt; jj += 2) {
                int nn = __shfl_sync(0xffffffffu, myn, jj + half);
                float4 v = src[(size_t)nn * 32 + l16];
                acc.x += v.x; acc.y += v.y; acc.z += v.z; acc.w += v.w;
            }
            if (jj < cnt) {  // odd tail: half 0 only
                int nn = __shfl_sync(0xffffffffu, myn, cnt - 1);
                if (half == 0) {
                    float4 v = src[(size_t)nn * 32 + l16];
                    acc.x += v.x; acc.y += v.y; acc.z += v.z; acc.w += v.w;
                }
            }
        }
        acc.x += __shfl_xor_sync(0xffffffffu, acc.x, 16);
        acc.y += __shfl_xor_sync(0xffffffffu, acc.y, 16);
        acc.z += __shfl_xor_sync(0xffffffffu, acc.z, 16);
        acc.w += __shfl_xor_sync(0xffffffffu, acc.w, 16);
        if (half == 0) {
            float inv = 1.f / (float)max(s1 - s0, 1);
            *reinterpret_cast<float4*>(dst + (size_t)i * 128 + 4 * l16) =
                make_float4(acc.x * inv, acc.y * inv, acc.z * inv, acc.w * inv);
        }
    }
}

// ---------------- combined dense transform (U and M segments in one launch) ----------------
// out = act[N][128] @ [Wl;Wr][128][64] + bl (+relu).
// Tile: 128 nodes/block. Warp w -> cols 8w..8w+7; lane -> nodes 4*lane..4*lane+3.
#define XF_SMEM (128 * 132 * 4 + 128 * 32 * 8 + 32 * 8)
__global__ __launch_bounds__(256) void k_xform2(
    const float4* __restrict__ actU, const float4* __restrict__ actM,
    const float* __restrict__ WlU, const float* __restrict__ WrU,
    const float* __restrict__ blU,
    const float* __restrict__ WlM, const float* __restrict__ WrM,
    const float* __restrict__ blM,
    float* __restrict__ outU, float* __restrict__ outM,
    int opitch, int NU, int NM, int XU, int doRelu) {
    extern __shared__ char smem[];
    float* sAct = reinterpret_cast<float*>(smem);                      // [128][132]
    unsigned long long* sW =
        reinterpret_cast<unsigned long long*>(smem + 128 * 132 * 4);   // [128][32]
    unsigned long long* sB =
        reinterpret_cast<unsigned long long*>(smem + 128 * 132 * 4 + 128 * 32 * 8);

    int segU = (int)blockIdx.x < XU;
    const float4* act = segU ? actU : actM;
    const float* Wl = segU ? WlU : WlM;
    const float* Wr = segU ? WrU : WrM;
    const float* bl = segU ? blU : blM;
    float* out = segU ? outU : outM;
    int N = segU ? NU : NM;
    int n0 = (segU ? blockIdx.x : blockIdx.x - XU) * 128;

    int t = threadIdx.x;
    int lane = t & 31, warp = t >> 5;

    // stage weights: sW[k*32+cp] = {W[k][2cp], W[k][2cp+1]}, W = [Wl;Wr]
    for (int idx = t; idx < 128 * 32; idx += 256) {
        int k = idx >> 5, cp = idx & 31;
        const float* Wg = (k < 64) ? (Wl + k * HD) : (Wr + (k - 64) * HD);
        float2 wv = *reinterpret_cast<const float2*>(Wg + 2 * cp);
        sW[idx] = pack2(wv.x, wv.y);
    }
    if (t < 32) sB[t] = pack2(bl[2 * t], bl[2 * t + 1]);

    // stage act transposed: sAct[k][n], 4x4 register transpose per thread
    for (int rg = warp; rg < 32; rg += 8) {
        int i0 = rg * 4;
        float4 z = make_float4(0.f, 0.f, 0.f, 0.f);
        float4 v0 = (n0 + i0 + 0 < N) ? act[(size_t)(n0 + i0 + 0) * 32 + lane] : z;
        float4 v1 = (n0 + i0 + 1 < N) ? act[(size_t)(n0 + i0 + 1) * 32 + lane] : z;
        float4 v2 = (n0 + i0 + 2 < N) ? act[(size_t)(n0 + i0 + 2) * 32 + lane] : z;
        float4 v3 = (n0 + i0 + 3 < N) ? act[(size_t)(n0 + i0 + 3) * 32 + lane] : z;
        *reinterpret_cast<float4*>(sAct + (4 * lane + 0) * 132 + i0) =
            make_float4(v0.x, v1.x, v2.x, v3.x);
        *reinterpret_cast<float4*>(sAct + (4 * lane + 1) * 132 + i0) =
            make_float4(v0.y, v1.y, v2.y, v3.y);
        *reinterpret_cast<float4*>(sAct + (4 * lane + 2) * 132 + i0) =
            make_float4(v0.z, v1.z, v2.z, v3.z);
        *reinterpret_cast<float4*>(sAct + (4 * lane + 3) * 132 + i0) =
            make_float4(v0.w, v1.w, v2.w, v3.w);
    }
    __syncthreads();

    unsigned long long acc[4][4];
#pragma unroll
    for (int n = 0; n < 4; n++)
#pragma unroll
        for (int j = 0; j < 4; j++) acc[n][j] = sB[4 * warp + j];

    const unsigned long long* wbase = sW + 4 * warp;
    const float* abase = sAct + 4 * lane;
#pragma unroll 4
    for (int k = 0; k < 128; k++) {
        float4 a = *reinterpret_cast<const float4*>(abase + k * 132);
        ulonglong2 w01 = *reinterpret_cast<const ulonglong2*>(wbase + (size_t)k * 32);
        ulonglong2 w23 = *reinterpret_cast<const ulonglong2*>(wbase + (size_t)k * 32 + 2);
        unsigned long long ax = pack2(a.x, a.x);
        unsigned long long ay = pack2(a.y, a.y);
        unsigned long long az = pack2(a.z, a.z);
        unsigned long long aw = pack2(a.w, a.w);
        ffma2(acc[0][0], ax, w01.x); ffma2(acc[0][1], ax, w01.y);
        ffma2(acc[0][2], ax, w23.x); ffma2(acc[0][3], ax, w23.y);
        ffma2(acc[1][0], ay, w01.x); ffma2(acc[1][1], ay, w01.y);
        ffma2(acc[1][2], ay, w23.x); ffma2(acc[1][3], ay, w23.y);
        ffma2(acc[2][0], az, w01.x); ffma2(acc[2][1], az, w01.y);
        ffma2(acc[2][2], az, w23.x); ffma2(acc[2][3], az, w23.y);
        ffma2(acc[3][0], aw, w01.x); ffma2(acc[3][1], aw, w01.y);
        ffma2(acc[3][2], aw, w23.x); ffma2(acc[3][3], aw, w23.y);
    }

#pragma unroll
    for (int n = 0; n < 4; n++) {
        int gn = n0 + 4 * lane + n;
        if (gn >= N) continue;
        float2 p0 = unpack2(acc[n][0]);
        float2 p1 = unpack2(acc[n][1]);
        float2 p2 = unpack2(acc[n][2]);
        float2 p3 = unpack2(acc[n][3]);
        if (doRelu) {
            p0.x = fmaxf(p0.x, 0.f); p0.y = fmaxf(p0.y, 0.f);
            p1.x = fmaxf(p1.x, 0.f); p1.y = fmaxf(p1.y, 0.f);
            p2.x = fmaxf(p2.x, 0.f); p2.y = fmaxf(p2.y, 0.f);
            p3.x = fmaxf(p3.x, 0.f); p3.y = fmaxf(p3.y, 0.f);
        }
        *reinterpret_cast<float4*>(out + (size_t)gn * opitch + 8 * warp) =
            make_float4(p0.x, p0.y, p1.x, p1.y);
        *reinterpret_cast<float4*>(out + (size_t)gn * opitch + 8 * warp + 4) =
            make_float4(p2.x, p2.y, p3.x, p3.y);
    }
}

// ---------------- final: edge classifier + scratch re-zero ----------------
__global__ __launch_bounds__(256) void k_classify(const int* uw, const void* els,
                                                  const void* eld,
                                                  const float* __restrict__ W,
                                                  const float* __restrict__ b,
                                                  float* __restrict__ out, int EL,
                                                  int GZ, int GC) {
    if ((int)blockIdx.x < GZ) {
        int i = blockIdx.x * 256 + threadIdx.x;
        if (i < NTOT) d_deg[i] = 0;
        else if (i < NTOT + 512) d_lb_flag[i - NTOT] = 0;
        return;
    }
    int f64 = detect64(uw);
    int lane = threadIdx.x & 31, warp = threadIdx.x >> 5;
    const float* u2 = reinterpret_cast<const float*>(d_u2o);
    const float* m2 = reinterpret_cast<const float*>(d_m2o);
    float w0[CN], w1[CN], w2[CN], w3[CN];
#pragma unroll
    for (int c = 0; c < CN; c++) {
        w0[c] = W[(2 * lane) * CN + c];
        w1[c] = W[(2 * lane + 1) * CN + c];
        w2[c] = W[(HD + 2 * lane) * CN + c];
        w3[c] = W[(HD + 2 * lane + 1) * CN + c];
    }
    int cb = blockIdx.x - GZ;
    for (int e = cb * 8 + warp; e < EL; e += GC * 8) {
        int s = ldidx(els, e, f64);
        int d = ldidx(eld, e, f64);
        float2 fu = *reinterpret_cast<const float2*>(u2 + (size_t)s * HD + 2 * lane);
        float2 fm = *reinterpret_cast<const float2*>(m2 + (size_t)d * HD + 2 * lane);
        float acc[CN];
#pragma unroll
        for (int c = 0; c < CN; c++)
            acc[c] = fu.x * w0[c] + fu.y * w1[c] + fm.x * w2[c] + fm.y * w3[c];
#pragma unroll
        for (int o = 16; o > 0; o >>= 1) {
#pragma unroll
            for (int c = 0; c < CN; c++)
                acc[c] += __shfl_down_sync(0xffffffffu, acc[c], o);
        }
        if (lane == 0) {
#pragma unroll
            for (int c = 0; c < CN; c++) out[(size_t)e * CN + c] = acc[c] + b[c];
        }
    }
}

// ---------------- host launch ----------------
extern "C" void kernel_launch(void* const* d_in, const int* in_sizes, int n_in,
                              void* d_out, int out_size) {
    const int* uw = (const int*)d_in[0];
    const void* unid = d_in[0];
    const void* mnid = d_in[1];
    const float* movie_x = (const float*)d_in[2];
    const void* esrc = d_in[3];
    const void* edst = d_in[4];
    const void* elsrc = d_in[5];
    const void* eldst = d_in[6];
    const float* user_emb = (const float*)d_in[7];
    const float* movie_emb = (const float*)d_in[8];
    const float* w_movie = (const float*)d_in[9];
    const float* b_movie = (const float*)d_in[10];

    int U = in_sizes[0];
    int M = in_sizes[1];
    int E = in_sizes[3];
    int EL = in_sizes[5];
    int F = in_sizes[2] / M;
    (void)n_in; (void)out_size;

    void *p_off_u, *p_off_m, *p_nbr_u, *p_nbr_m;
    void *p_au1, *p_am1, *p_au2, *p_am2, *p_u2o, *p_m2o;
    cudaGetSymbolAddress(&p_off_u, d_off_u);
    cudaGetSymbolAddress(&p_off_m, d_off_m);
    cudaGetSymbolAddress(&p_nbr_u, d_nbr_u);
    cudaGetSymbolAddress(&p_nbr_m, d_nbr_m);
    cudaGetSymbolAddress(&p_au1, d_act_u1);
    cudaGetSymbolAddress(&p_am1, d_act_m1);
    cudaGetSymbolAddress(&p_au2, d_act_u2);
    cudaGetSymbolAddress(&p_am2, d_act_m2);
    cudaGetSymbolAddress(&p_u2o, d_u2o);
    cudaGetSymbolAddress(&p_m2o, d_m2o);

    cudaFuncSetAttribute(k_xform2, cudaFuncAttributeMaxDynamicSharedMemorySize, XF_SMEM);

    float* au1 = (float*)p_au1;
    float* am1 = (float*)p_am1;
    float* au2 = (float*)p_au2;
    float* am2 = (float*)p_am2;
    const int* off_u = (const int*)p_off_u;
    const int* off_m = (const int*)p_off_m;
    const int* nbr_u = (const int*)p_nbr_u;
    const int* nbr_m = (const int*)p_nbr_m;

    // 0: prep (gather user + movie proj + degree count)
    int GG = (U * 16 + 255) / 256;
    int GM = 1024;
    int GC = 2048;
    k_prep<<<GG + GM + GC, 256>>>(uw, unid, mnid, user_emb, movie_x, w_movie,
                                  b_movie, movie_emb, esrc, edst,
                                  U, M, F, E, GG, GM, GC);
    // 1: scan (decoupled lookback)
    int NB = (U + M + 4095) / 4096;
    k_scan_lb<<<NB, 1024>>>(U, M, E);
    // 2: fill
    k_fill<<<2048, 256>>>(uw, esrc, edst, E);

    const int GB = 1776;
    int XU = (U + 127) / 128, XM = (M + 127) / 128;

    // 3: combined gather layer 1 (u1 agg <- x_movie; m1 agg <- x_user)  [ncu target]
    k_gather2<<<GB, 256>>>((const float4*)(am1 + 64), au1, off_u, nbr_u, U,
                           (const float4*)(au1 + 64), am1, off_m, nbr_m, M);
    // 4: combined xform layer 1 (relu) -> xd slots of layer-2 act buffers
    k_xform2<<<XU + XM, 256, XF_SMEM>>>(
        (const float4*)p_au1, (const float4*)p_am1,
        (const float*)d_in[14], (const float*)d_in[16], (const float*)d_in[15],
        (const float*)d_in[11], (const float*)d_in[13], (const float*)d_in[12],
        au2 + 64, am2 + 64, 128, U, M, XU, 1);
    // 5: combined gather layer 2 (u2 agg <- m1; m2 agg <- u1)
    k_gather2<<<GB, 256>>>((const float4*)(am2 + 64), au2, off_u, nbr_u, U,
                           (const float4*)(au2 + 64), am2, off_m, nbr_m, M);
    // 6: combined xform layer 2 (no relu) -> final u2o/m2o
    k_xform2<<<XU + XM, 256, XF_SMEM>>>(
        (const float4*)p_au2, (const float4*)p_am2,
        (const float*)d_in[20], (const float*)d_in[22], (const float*)d_in[21],
        (const float*)d_in[17], (const float*)d_in[19], (const float*)d_in[18],
        (float*)p_u2o, (float*)p_m2o, 64, U, M, XU, 0);
    // 7: classifier + scratch re-zero
    int GZ = (NTOT + 512 + 255) / 256;
    k_classify<<<GZ + 2048, 256>>>(uw, elsrc, eldst, (const float*)d_in[23],
                                   (const float*)d_in[24], (float*)d_out, EL,
                                   GZ, 2048);
}

// round 6
// speedup vs baseline: 1.0958x; 1.0958x over previous
#include <cuda_runtime.h>

#define U_N 200000
#define M_N 100000
#define E_N 2000000
#define HD 64
#define CN 7
#define NTOT (U_N + M_N)

// ---------------- device scratch (static; zero-initialized at module load) ----------------
// d_deg and d_lb_flag are re-zeroed at the END of every kernel_launch (tail
// blocks of k_classify), so every graph replay starts from a clean state.
__device__ int d_deg[NTOT];
__device__ int d_off_u[U_N + 1];
__device__ int d_off_m[M_N + 1];
__device__ int d_cur_u[U_N];
__device__ int d_cur_m[M_N];
__device__ int d_nbr_u[E_N];
__device__ int d_nbr_m[E_N];
__device__ volatile int d_lb_flag[512];
__device__ int d_lb_agg[512];
__device__ int d_lb_inc[512];
// compact [N][64] feature buffers (float4[N][16])
__device__ float4 d_xu[(size_t)U_N * 16];     // x_user
__device__ float4 d_xm[(size_t)M_N * 16];     // x_movie
__device__ float4 d_agg_u[(size_t)U_N * 16];  // mean-agg into users (both layers)
__device__ float4 d_agg_m[(size_t)M_N * 16];  // mean-agg into movies (both layers)
__device__ float4 d_u1[(size_t)U_N * 16];
__device__ float4 d_m1[(size_t)M_N * 16];
__device__ float4 d_u2o[(size_t)U_N * 16];
__device__ float4 d_m2o[(size_t)M_N * 16];

// ---------------- helpers ----------------
__device__ __forceinline__ int ldidx(const void* p, int i, int f64) {
    return f64 ? (int)((const long long*)p)[i] : ((const int*)p)[i];
}
__device__ __forceinline__ int detect64(const int* uw) { return uw[3] == 0; }

__device__ __forceinline__ unsigned long long pack2(float x, float y) {
    unsigned long long r;
    asm("mov.b64 %0, {%1, %2};" : "=l"(r) : "f"(x), "f"(y));
    return r;
}
__device__ __forceinline__ float2 unpack2(unsigned long long v) {
    float2 r;
    asm("mov.b64 {%0, %1}, %2;" : "=f"(r.x), "=f"(r.y) : "l"(v));
    return r;
}
__device__ __forceinline__ void ffma2(unsigned long long& acc, unsigned long long a,
                                      unsigned long long w) {
    asm("fma.rn.f32x2 %0, %1, %2, %0;" : "+l"(acc) : "l"(a), "l"(w));
}

// ---------------- launch 0: user gather + movie projection + degree count ----------------
__global__ __launch_bounds__(256) void k_prep(
    const int* uw, const void* unid, const void* mnid,
    const float* ue, const float* mx, const float* W, const float* bb,
    const float* memb, const void* es, const void* ed,
    int U, int M, int F, int E, int GG, int GM, int GC) {
    __shared__ float2 sW[32 * 32];
    int f64 = detect64(uw);
    if ((int)blockIdx.x < GG) {
        // x_user = user_emb[user_node_id]
        int j = blockIdx.x * 256 + threadIdx.x;
        if (j < U * 16) {
            int node = j >> 4, q = j & 15;
            int uid = ldidx(unid, node, f64);
            d_xu[j] = reinterpret_cast<const float4*>(ue)[(size_t)uid * 16 + q];
        }
    } else if ((int)blockIdx.x < GG + GM) {
        // x_movie = movie_x @ w_movie + b + movie_emb[id]
        for (int idx = threadIdx.x; idx < F * 32; idx += 256) {
            int f = idx >> 5, t = idx & 31;
            sW[idx] = make_float2(W[f * HD + t], W[f * HD + t + 32]);
        }
        __syncthreads();
        int lane = threadIdx.x & 31, warp = threadIdx.x >> 5;
        int mb = blockIdx.x - GG;
        float* xm = reinterpret_cast<float*>(d_xm);
        for (int m = mb * 8 + warp; m < M; m += GM * 8) {
            float mxv = (lane < F) ? mx[(size_t)m * F + lane] : 0.f;
            int mid = ldidx(mnid, m, f64);
            float acc0 = bb[lane] + memb[(size_t)mid * HD + lane];
            float acc1 = bb[lane + 32] + memb[(size_t)mid * HD + lane + 32];
            for (int f = 0; f < F; f++) {
                float v = __shfl_sync(0xffffffffu, mxv, f);
                float2 wv = sW[f * 32 + lane];
                acc0 += v * wv.x;
                acc1 += v * wv.y;
            }
            xm[(size_t)m * HD + lane] = acc0;
            xm[(size_t)m * HD + lane + 32] = acc1;
        }
    } else {
        int cb = blockIdx.x - (GG + GM);
        for (int e = cb * 256 + threadIdx.x; e < E; e += GC * 256) {
            atomicAdd(&d_deg[ldidx(es, e, f64)], 1);
            atomicAdd(&d_deg[U + ldidx(ed, e, f64)], 1);
        }
    }
}

// ---------------- launch 1: decoupled-lookback scan over combined deg ----------------
__global__ __launch_bounds__(1024) void k_scan_lb(int U, int M, int E) {
    __shared__ int sh[1024];
    __shared__ int sRun;
    int n = U + M;
    int tid = threadIdx.x, bid = blockIdx.x;
    int base = bid * 4096 + tid * 4;
    int4 v = make_int4(0, 0, 0, 0);
    if (base + 3 < n)
        v = *reinterpret_cast<const int4*>(d_deg + base);
    else {
        if (base < n) v.x = d_deg[base];
        if (base + 1 < n) v.y = d_deg[base + 1];
        if (base + 2 < n) v.z = d_deg[base + 2];
    }
    int loc = v.x + v.y + v.z + v.w;
    sh[tid] = loc;
    __syncthreads();
    for (int o = 1; o < 1024; o <<= 1) {
        int a = (tid >= o) ? sh[tid - o] : 0;
        __syncthreads();
        sh[tid] += a;
        __syncthreads();
    }
    int incl = sh[tid];
    int bsum = sh[1023];
    if (tid == 0) {
        int run = 0;
        if (bid == 0) {
            d_lb_inc[0] = bsum;
            __threadfence();
            d_lb_flag[0] = 2;
        } else {
            d_lb_agg[bid] = bsum;
            __threadfence();
            d_lb_flag[bid] = 1;
            int p = bid - 1;
            while (true) {
                int f;
                while ((f = d_lb_flag[p]) == 0) {}
                __threadfence();
                if (f == 2) { run += d_lb_inc[p]; break; }
                run += d_lb_agg[p];
                p--;
            }
            d_lb_inc[bid] = run + bsum;
            __threadfence();
            d_lb_flag[bid] = 2;
        }
        sRun = run;
    }
    __syncthreads();
    int e = sRun + incl - loc;
    int vv[4] = {v.x, v.y, v.z, v.w};
#pragma unroll
    for (int w = 0; w < 4; w++) {
        int gi = base + w;
        if (gi < n) {
            if (gi < U) { d_off_u[gi] = e; d_cur_u[gi] = e; }
            else { d_off_m[gi - U] = e - E; d_cur_m[gi - U] = e - E; }
        }
        e += vv[w];
    }
    if (bid == 0 && tid == 0) { d_off_u[U] = E; d_off_m[M] = E; }
}

// ---------------- launch 2: fill adjacency ----------------
__global__ void k_fill(const int* uw, const void* es, const void* ed, int n) {
    int f64 = detect64(uw);
    for (int e = blockIdx.x * blockDim.x + threadIdx.x; e < n;
         e += gridDim.x * blockDim.x) {
        int s = ldidx(es, e, f64);
        int d = ldidx(ed, e, f64);
        d_nbr_u[atomicAdd(&d_cur_u[s], 1)] = d;
        d_nbr_m[atomicAdd(&d_cur_m[d], 1)] = s;
    }
}

// ---------------- gather: one direction per launch (L2-resident working set) ----------------
// Half-warp scheme: lanes 0-15 read neighbor A's 64-float row (1 float4 each),
// lanes 16-31 neighbor B; cross-half shfl_xor(16) reduce; lanes 0-15 store.
__global__ __launch_bounds__(256) void k_gather(const float4* __restrict__ src,
                                                float4* __restrict__ dst,
                                                const int* __restrict__ off,
                                                const int* __restrict__ nbr,
                                                int n_dst) {
    int lane = threadIdx.x & 31, warp = threadIdx.x >> 5;
    int half = lane >> 4, l16 = lane & 15;
    for (int i = blockIdx.x * 8 + warp; i < n_dst; i += gridDim.x * 8) {
        int s0 = off[i], s1 = off[i + 1];
        float4 acc = make_float4(0.f, 0.f, 0.f, 0.f);
        for (int j = s0; j < s1; j += 32) {
            int myn = (j + lane < s1) ? nbr[j + lane] : 0;
            int cnt = min(32, s1 - j);
            int jj = 0;
            for (; jj + 8 <= cnt; jj += 8) {
                int n0 = __shfl_sync(0xffffffffu, myn, jj + half);
                int n1 = __shfl_sync(0xffffffffu, myn, jj + 2 + half);
                int n2 = __shfl_sync(0xffffffffu, myn, jj + 4 + half);
                int n3 = __shfl_sync(0xffffffffu, myn, jj + 6 + half);
                float4 v0 = src[(size_t)n0 * 16 + l16];
                float4 v1 = src[(size_t)n1 * 16 + l16];
                float4 v2 = src[(size_t)n2 * 16 + l16];
                float4 v3 = src[(size_t)n3 * 16 + l16];
                acc.x += (v0.x + v1.x) + (v2.x + v3.x);
                acc.y += (v0.y + v1.y) + (v2.y + v3.y);
                acc.z += (v0.z + v1.z) + (v2.z + v3.z);
                acc.w += (v0.w + v1.w) + (v2.w + v3.w);
            }
            for (; jj + 2 <= cnt; jj += 2) {
                int nn = __shfl_sync(0xffffffffu, myn, jj + half);
                float4 v = src[(size_t)nn * 16 + l16];
                acc.x += v.x; acc.y += v.y; acc.z += v.z; acc.w += v.w;
            }
            if (jj < cnt) {  // odd tail: half 0 only
                int nn = __shfl_sync(0xffffffffu, myn, cnt - 1);
                if (half == 0) {
                    float4 v = src[(size_t)nn * 16 + l16];
                    acc.x += v.x; acc.y += v.y; acc.z += v.z; acc.w += v.w;
                }
            }
        }
        acc.x += __shfl_xor_sync(0xffffffffu, acc.x, 16);
        acc.y += __shfl_xor_sync(0xffffffffu, acc.y, 16);
        acc.z += __shfl_xor_sync(0xffffffffu, acc.z, 16);
        acc.w += __shfl_xor_sync(0xffffffffu, acc.w, 16);
        if (half == 0) {
            float inv = 1.f / (float)max(s1 - s0, 1);
            dst[(size_t)i * 16 + l16] =
                make_float4(acc.x * inv, acc.y * inv, acc.z * inv, acc.w * inv);
        }
    }
}

// ---------------- combined dense transform (U and M segments in one launch) ----------------
// out = [agg | xd][N][128] @ [Wl;Wr][128][64] + bl (+relu).
// Tile: 128 nodes/block. Warp w -> cols 8w..8w+7; lane -> nodes 4*lane..4*lane+3.
#define XF_SMEM (128 * 132 * 4 + 128 * 32 * 8 + 32 * 8)
__global__ __launch_bounds__(256) void k_xform2(
    const float4* __restrict__ aggU, const float4* __restrict__ xdU,
    const float4* __restrict__ aggM, const float4* __restrict__ xdM,
    const float* __restrict__ WlU, const float* __restrict__ WrU,
    const float* __restrict__ blU,
    const float* __restrict__ WlM, const float* __restrict__ WrM,
    const float* __restrict__ blM,
    float4* __restrict__ outU, float4* __restrict__ outM,
    int NU, int NM, int XU, int doRelu) {
    extern __shared__ char smem[];
    float* sAct = reinterpret_cast<float*>(smem);                      // [128][132]
    unsigned long long* sW =
        reinterpret_cast<unsigned long long*>(smem + 128 * 132 * 4);   // [128][32]
    unsigned long long* sB =
        reinterpret_cast<unsigned long long*>(smem + 128 * 132 * 4 + 128 * 32 * 8);

    int segU = (int)blockIdx.x < XU;
    const float4* agg = segU ? aggU : aggM;
    const float4* xd = segU ? xdU : xdM;
    const float* Wl = segU ? WlU : WlM;
    const float* Wr = segU ? WrU : WrM;
    const float* bl = segU ? blU : blM;
    float4* out = segU ? outU : outM;
    int N = segU ? NU : NM;
    int n0 = (segU ? blockIdx.x : blockIdx.x - XU) * 128;

    int t = threadIdx.x;
    int lane = t & 31, warp = t >> 5;

    // stage weights: sW[k*32+cp] = {W[k][2cp], W[k][2cp+1]}, W = [Wl;Wr]
    for (int idx = t; idx < 128 * 32; idx += 256) {
        int k = idx >> 5, cp = idx & 31;
        const float* Wg = (k < 64) ? (Wl + k * HD) : (Wr + (k - 64) * HD);
        float2 wv = *reinterpret_cast<const float2*>(Wg + 2 * cp);
        sW[idx] = pack2(wv.x, wv.y);
    }
    if (t < 32) sB[t] = pack2(bl[2 * t], bl[2 * t + 1]);

    // stage act transposed: sAct[k][n]; k<64 from agg, k>=64 from xd
    for (int rg = warp; rg < 32; rg += 8) {
        int i0 = rg * 4;
        float4 z = make_float4(0.f, 0.f, 0.f, 0.f);
        const float4* base = (lane < 16) ? agg : xd;
        int q = lane & 15;
        float4 v0 = (n0 + i0 + 0 < N) ? base[(size_t)(n0 + i0 + 0) * 16 + q] : z;
        float4 v1 = (n0 + i0 + 1 < N) ? base[(size_t)(n0 + i0 + 1) * 16 + q] : z;
        float4 v2 = (n0 + i0 + 2 < N) ? base[(size_t)(n0 + i0 + 2) * 16 + q] : z;
        float4 v3 = (n0 + i0 + 3 < N) ? base[(size_t)(n0 + i0 + 3) * 16 + q] : z;
        *reinterpret_cast<float4*>(sAct + (4 * lane + 0) * 132 + i0) =
            make_float4(v0.x, v1.x, v2.x, v3.x);
        *reinterpret_cast<float4*>(sAct + (4 * lane + 1) * 132 + i0) =
            make_float4(v0.y, v1.y, v2.y, v3.y);
        *reinterpret_cast<float4*>(sAct + (4 * lane + 2) * 132 + i0) =
            make_float4(v0.z, v1.z, v2.z, v3.z);
        *reinterpret_cast<float4*>(sAct + (4 * lane + 3) * 132 + i0) =
            make_float4(v0.w, v1.w, v2.w, v3.w);
    }
    __syncthreads();

    unsigned long long acc[4][4];
#pragma unroll
    for (int n = 0; n < 4; n++)
#pragma unroll
        for (int j = 0; j < 4; j++) acc[n][j] = sB[4 * warp + j];

    const unsigned long long* wbase = sW + 4 * warp;
    const float* abase = sAct + 4 * lane;
#pragma unroll 4
    for (int k = 0; k < 128; k++) {
        float4 a = *reinterpret_cast<const float4*>(abase + k * 132);
        ulonglong2 w01 = *reinterpret_cast<const ulonglong2*>(wbase + (size_t)k * 32);
        ulonglong2 w23 = *reinterpret_cast<const ulonglong2*>(wbase + (size_t)k * 32 + 2);
        unsigned long long ax = pack2(a.x, a.x);
        unsigned long long ay = pack2(a.y, a.y);
        unsigned long long az = pack2(a.z, a.z);
        unsigned long long aw = pack2(a.w, a.w);
        ffma2(acc[0][0], ax, w01.x); ffma2(acc[0][1], ax, w01.y);
        ffma2(acc[0][2], ax, w23.x); ffma2(acc[0][3], ax, w23.y);
        ffma2(acc[1][0], ay, w01.x); ffma2(acc[1][1], ay, w01.y);
        ffma2(acc[1][2], ay, w23.x); ffma2(acc[1][3], ay, w23.y);
        ffma2(acc[2][0], az, w01.x); ffma2(acc[2][1], az, w01.y);
        ffma2(acc[2][2], az, w23.x); ffma2(acc[2][3], az, w23.y);
        ffma2(acc[3][0], aw, w01.x); ffma2(acc[3][1], aw, w01.y);
        ffma2(acc[3][2], aw, w23.x); ffma2(acc[3][3], aw, w23.y);
    }

#pragma unroll
    for (int n = 0; n < 4; n++) {
        int gn = n0 + 4 * lane + n;
        if (gn >= N) continue;
        float2 p0 = unpack2(acc[n][0]);
        float2 p1 = unpack2(acc[n][1]);
        float2 p2 = unpack2(acc[n][2]);
        float2 p3 = unpack2(acc[n][3]);
        if (doRelu) {
            p0.x = fmaxf(p0.x, 0.f); p0.y = fmaxf(p0.y, 0.f);
            p1.x = fmaxf(p1.x, 0.f); p1.y = fmaxf(p1.y, 0.f);
            p2.x = fmaxf(p2.x, 0.f); p2.y = fmaxf(p2.y, 0.f);
            p3.x = fmaxf(p3.x, 0.f); p3.y = fmaxf(p3.y, 0.f);
        }
        out[(size_t)gn * 16 + 2 * warp] = make_float4(p0.x, p0.y, p1.x, p1.y);
        out[(size_t)gn * 16 + 2 * warp + 1] = make_float4(p2.x, p2.y, p3.x, p3.y);
    }
}

// ---------------- final: edge classifier + scratch re-zero ----------------
__global__ __launch_bounds__(256) void k_classify(const int* uw, const void* els,
                                                  const void* eld,
                                                  const float* __restrict__ W,
                                                  const float* __restrict__ b,
                                                  float* __restrict__ out, int EL,
                                                  int GZ, int GC) {
    if ((int)blockIdx.x < GZ) {
        int i = blockIdx.x * 256 + threadIdx.x;
        if (i < NTOT) d_deg[i] = 0;
        else if (i < NTOT + 512) d_lb_flag[i - NTOT] = 0;
        return;
    }
    int f64 = detect64(uw);
    int lane = threadIdx.x & 31, warp = threadIdx.x >> 5;
    const float* u2 = reinterpret_cast<const float*>(d_u2o);
    const float* m2 = reinterpret_cast<const float*>(d_m2o);
    float w0[CN], w1[CN], w2[CN], w3[CN];
#pragma unroll
    for (int c = 0; c < CN; c++) {
        w0[c] = W[(2 * lane) * CN + c];
        w1[c] = W[(2 * lane + 1) * CN + c];
        w2[c] = W[(HD + 2 * lane) * CN + c];
        w3[c] = W[(HD + 2 * lane + 1) * CN + c];
    }
    int cb = blockIdx.x - GZ;
    for (int e = cb * 8 + warp; e < EL; e += GC * 8) {
        int s = ldidx(els, e, f64);
        int d = ldidx(eld, e, f64);
        float2 fu = *reinterpret_cast<const float2*>(u2 + (size_t)s * HD + 2 * lane);
        float2 fm = *reinterpret_cast<const float2*>(m2 + (size_t)d * HD + 2 * lane);
        float acc[CN];
#pragma unroll
        for (int c = 0; c < CN; c++)
            acc[c] = fu.x * w0[c] + fu.y * w1[c] + fm.x * w2[c] + fm.y * w3[c];
#pragma unroll
        for (int o = 16; o > 0; o >>= 1) {
#pragma unroll
            for (int c = 0; c < CN; c++)
                acc[c] += __shfl_down_sync(0xffffffffu, acc[c], o);
        }
        if (lane == 0) {
#pragma unroll
            for (int c = 0; c < CN; c++) out[(size_t)e * CN + c] = acc[c] + b[c];
        }
    }
}

// ---------------- host launch ----------------
extern "C" void kernel_launch(void* const* d_in, const int* in_sizes, int n_in,
                              void* d_out, int out_size) {
    const int* uw = (const int*)d_in[0];
    const void* unid = d_in[0];
    const void* mnid = d_in[1];
    const float* movie_x = (const float*)d_in[2];
    const void* esrc = d_in[3];
    const void* edst = d_in[4];
    const void* elsrc = d_in[5];
    const void* eldst = d_in[6];
    const float* user_emb = (const float*)d_in[7];
    const float* movie_emb = (const float*)d_in[8];
    const float* w_movie = (const float*)d_in[9];
    const float* b_movie = (const float*)d_in[10];

    int U = in_sizes[0];
    int M = in_sizes[1];
    int E = in_sizes[3];
    int EL = in_sizes[5];
    int F = in_sizes[2] / M;
    (void)n_in; (void)out_size;

    void *p_off_u, *p_off_m, *p_nbr_u, *p_nbr_m;
    void *p_xu, *p_xm, *p_agg_u, *p_agg_m, *p_u1, *p_m1, *p_u2o, *p_m2o;
    cudaGetSymbolAddress(&p_off_u, d_off_u);
    cudaGetSymbolAddress(&p_off_m, d_off_m);
    cudaGetSymbolAddress(&p_nbr_u, d_nbr_u);
    cudaGetSymbolAddress(&p_nbr_m, d_nbr_m);
    cudaGetSymbolAddress(&p_xu, d_xu);
    cudaGetSymbolAddress(&p_xm, d_xm);
    cudaGetSymbolAddress(&p_agg_u, d_agg_u);
    cudaGetSymbolAddress(&p_agg_m, d_agg_m);
    cudaGetSymbolAddress(&p_u1, d_u1);
    cudaGetSymbolAddress(&p_m1, d_m1);
    cudaGetSymbolAddress(&p_u2o, d_u2o);
    cudaGetSymbolAddress(&p_m2o, d_m2o);

    cudaFuncSetAttribute(k_xform2, cudaFuncAttributeMaxDynamicSharedMemorySize, XF_SMEM);

    const int* off_u = (const int*)p_off_u;
    const int* off_m = (const int*)p_off_m;
    const int* nbr_u = (const int*)p_nbr_u;
    const int* nbr_m = (const int*)p_nbr_m;

    // 0: prep (x_user gather + x_movie proj + degree count)
    int GG = (U * 16 + 255) / 256;
    int GM = 1024;
    int GC = 2048;
    k_prep<<<GG + GM + GC, 256>>>(uw, unid, mnid, user_emb, movie_x, w_movie,
                                  b_movie, movie_emb, esrc, edst,
                                  U, M, F, E, GG, GM, GC);
    // 1: scan (decoupled lookback)
    int NB = (U + M + 4095) / 4096;
    k_scan_lb<<<NB, 1024>>>(U, M, E);
    // 2: fill
    k_fill<<<2048, 256>>>(uw, esrc, edst, E);

    const int GB = 1776;
    int XU = (U + 127) / 128, XM = (M + 127) / 128;

    // 3: gather layer1 U (agg_u <- x_movie)  [ncu target]
    k_gather<<<GB, 256>>>((const float4*)p_xm, (float4*)p_agg_u, off_u, nbr_u, U);
    // 4: gather layer1 M (agg_m <- x_user)
    k_gather<<<GB, 256>>>((const float4*)p_xu, (float4*)p_agg_m, off_m, nbr_m, M);
    // 5: combined xform layer1 (relu) -> u1/m1
    k_xform2<<<XU + XM, 256, XF_SMEM>>>(
        (const float4*)p_agg_u, (const float4*)p_xu,
        (const float4*)p_agg_m, (const float4*)p_xm,
        (const float*)d_in[14], (const float*)d_in[16], (const float*)d_in[15],
        (const float*)d_in[11], (const float*)d_in[13], (const float*)d_in[12],
        (float4*)p_u1, (float4*)p_m1, U, M, XU, 1);
    // 6: gather layer2 U (agg_u <- m1)
    k_gather<<<GB, 256>>>((const float4*)p_m1, (float4*)p_agg_u, off_u, nbr_u, U);
    // 7: gather layer2 M (agg_m <- u1)
    k_gather<<<GB, 256>>>((const float4*)p_u1, (float4*)p_agg_m, off_m, nbr_m, M);
    // 8: combined xform layer2 (no relu) -> u2o/m2o
    k_xform2<<<XU + XM, 256, XF_SMEM>>>(
        (const float4*)p_agg_u, (const float4*)p_u1,
        (const float4*)p_agg_m, (const float4*)p_m1,
        (const float*)d_in[20], (const float*)d_in[22], (const float*)d_in[21],
        (const float*)d_in[17], (const float*)d_in[19], (const float*)d_in[18],
        (float4*)p_u2o, (float4*)p_m2o, U, M, XU, 0);
    // 9: classifier + scratch re-zero
    int GZ = (NTOT + 512 + 255) / 256;
    k_classify<<<GZ + 2048, 256>>>(uw, elsrc, eldst, (const float*)d_in[23],
                                   (const float*)d_in[24], (float*)d_out, EL,
                                   GZ, 2048);
}